// round 1
// baseline (speedup 1.0000x reference)
#include <cuda_runtime.h>
#include <math.h>

// Problem constants
#define SEQ   4096
#define DMODEL 2048
#define NHEAD 16
#define NKV   4
#define HDIM  128
#define NKVD  512     // NKV * HDIM
#define SCALE 0.08838834764831845f   // 1/sqrt(128)

// Scratch (device globals; no allocation allowed)
__device__ float g_Q[SEQ * DMODEL];
__device__ float g_K[SEQ * NKVD];
__device__ float g_V[SEQ * NKVD];
__device__ float g_AO[SEQ * DMODEL];
__device__ float g_cos[SEQ * 64];
__device__ float g_sin[SEQ * 64];

// ----------------------------------------------------------------------------
// SGEMM: C[M,N] = A[M,K] @ B[K,N], row-major. 128x128 block, BK=16, 8x8 micro.
// M mult of 128, N mult of 128, K mult of 16.
// ----------------------------------------------------------------------------
__global__ __launch_bounds__(256) void sgemm128(const float* __restrict__ A,
                                                const float* __restrict__ B,
                                                float* __restrict__ C,
                                                int M, int N, int K) {
    __shared__ float As[16][132];   // transposed A tile, padded
    __shared__ float Bs[16][128];

    const int tid = threadIdx.x;
    const int bm = blockIdx.y * 128;
    const int bn = blockIdx.x * 128;
    const int tx = tid & 15;        // col group (n0 = 8*tx)
    const int ty = tid >> 4;        // row group (m0 = 8*ty)

    const int ar = tid >> 2;            // A tile row (0..63), +64 for 2nd f4
    const int ac = (tid & 3) * 4;       // A tile col (k within tile)
    const int bk = tid >> 5;            // B tile row (0..7), +8 for 2nd f4
    const int bc = (tid & 31) * 4;      // B tile col

    float acc[8][8];
#pragma unroll
    for (int i = 0; i < 8; i++)
#pragma unroll
        for (int j = 0; j < 8; j++) acc[i][j] = 0.f;

    for (int k0 = 0; k0 < K; k0 += 16) {
        float4 a0 = *(const float4*)(A + (size_t)(bm + ar) * K + k0 + ac);
        float4 a1 = *(const float4*)(A + (size_t)(bm + ar + 64) * K + k0 + ac);
        float4 b0 = *(const float4*)(B + (size_t)(k0 + bk) * N + bn + bc);
        float4 b1 = *(const float4*)(B + (size_t)(k0 + bk + 8) * N + bn + bc);

        __syncthreads();
        As[ac + 0][ar] = a0.x; As[ac + 1][ar] = a0.y;
        As[ac + 2][ar] = a0.z; As[ac + 3][ar] = a0.w;
        As[ac + 0][ar + 64] = a1.x; As[ac + 1][ar + 64] = a1.y;
        As[ac + 2][ar + 64] = a1.z; As[ac + 3][ar + 64] = a1.w;
        *(float4*)&Bs[bk][bc]     = b0;
        *(float4*)&Bs[bk + 8][bc] = b1;
        __syncthreads();

#pragma unroll
        for (int kk = 0; kk < 16; kk++) {
            float a[8], b[8];
            *(float4*)&a[0] = *(float4*)&As[kk][ty * 8];
            *(float4*)&a[4] = *(float4*)&As[kk][ty * 8 + 4];
            *(float4*)&b[0] = *(float4*)&Bs[kk][tx * 8];
            *(float4*)&b[4] = *(float4*)&Bs[kk][tx * 8 + 4];
#pragma unroll
            for (int i = 0; i < 8; i++)
#pragma unroll
                for (int j = 0; j < 8; j++)
                    acc[i][j] += a[i] * b[j];
        }
    }

#pragma unroll
    for (int i = 0; i < 8; i++) {
        float4 o0 = make_float4(acc[i][0], acc[i][1], acc[i][2], acc[i][3]);
        float4 o1 = make_float4(acc[i][4], acc[i][5], acc[i][6], acc[i][7]);
        float* crow = C + (size_t)(bm + ty * 8 + i) * N + bn + tx * 8;
        *(float4*)(crow)     = o0;
        *(float4*)(crow + 4) = o1;
    }
}

// ----------------------------------------------------------------------------
// RoPE cos/sin table: computed in double so angle error vs reference stays tiny
// ----------------------------------------------------------------------------
__global__ void rope_table_kernel() {
    int idx = blockIdx.x * blockDim.x + threadIdx.x;   // SEQ*64 threads
    if (idx >= SEQ * 64) return;
    int pos = idx >> 6;
    int d = idx & 63;
    double inv = exp(-(double)d * (log(10000.0) / 64.0));
    double ang = (double)pos * inv;
    double s, c;
    sincos(ang, &s, &c);
    g_cos[idx] = (float)c;
    g_sin[idx] = (float)s;
}

// Apply RoPE in place to Q [SEQ, 16*128] and K [SEQ, 4*128]
__global__ __launch_bounds__(256) void rope_apply_kernel() {
    int pos = blockIdx.x;
    int tid = threadIdx.x;
    const float* ct = g_cos + pos * 64;
    const float* st = g_sin + pos * 64;

    float* qrow = g_Q + (size_t)pos * DMODEL;
#pragma unroll
    for (int it = 0; it < 4; it++) {
        int p = tid + it * 256;            // 1024 pairs
        int head = p >> 6, d = p & 63;
        float c = ct[d], s = st[d];
        float* base = qrow + head * HDIM;
        float xr = base[d], xi = base[d + 64];
        base[d]      = xr * c - xi * s;
        base[d + 64] = xr * s + xi * c;
    }
    {
        int p = tid;                        // 256 pairs
        int head = p >> 6, d = p & 63;
        float c = ct[d], s = st[d];
        float* base = g_K + (size_t)pos * NKVD + head * HDIM;
        float xr = base[d], xi = base[d + 64];
        base[d]      = xr * c - xi * s;
        base[d + 64] = xr * s + xi * c;
    }
}

// ----------------------------------------------------------------------------
// Flash attention (non-causal, GQA 4:1). Block = 64 queries x 1 head.
// 256 threads. Streams over 64 key tiles of 64.
// ----------------------------------------------------------------------------
#define QS_STRIDE 132
#define PS_STRIDE 68
#define ATTN_SMEM_FLOATS (64*QS_STRIDE + 64*QS_STRIDE + 64*128 + 64*PS_STRIDE + 192)

__global__ __launch_bounds__(256) void attn_kernel(const float* __restrict__ Qg,
                                                   const float* __restrict__ Kg,
                                                   const float* __restrict__ Vg,
                                                   float* __restrict__ Og) {
    extern __shared__ float sm[];
    float* Qs = sm;                          // [64][132]
    float* Ks = Qs + 64 * QS_STRIDE;         // [64][132]
    float* Vs = Ks + 64 * QS_STRIDE;         // [64][128]
    float* Ps = Vs + 64 * 128;               // [64][68]
    float* ms = Ps + 64 * PS_STRIDE;         // [64]
    float* ls = ms + 64;                     // [64]
    float* als = ls + 64;                    // [64]

    const int tid = threadIdx.x;
    const int q0 = blockIdx.x * 64;
    const int h = blockIdx.y;
    const int kvh = h >> 2;                  // repeat along head axis: h//4

    // tile-load mapping: 2048 float4s / 256 threads = 8 each
    const int fr = tid >> 5;                 // base row, step 8
    const int fc = (tid & 31) * 4;           // col

    // score phase: warp-2D 8x4 layout (rows x cols) to keep banks distinct
    const int lane = tid & 31, w = tid >> 5;
    const int sr0 = ((w & 1) * 8 + (lane >> 2)) * 4;    // 0..60
    const int sc0 = ((w >> 1) * 4 + (lane & 3)) * 4;    // 0..60
    // softmax phase: quad per row
    const int srow = tid >> 2;
    const int sseg = (tid & 3) * 16;
    // PV phase: 16x16 layout, 4 rows x 8 cols micro
    const int pr0 = (tid >> 4) * 4;
    const int pc0 = (tid & 15) * 8;

    // Load Q tile (scaled)
#pragma unroll
    for (int i = 0; i < 8; i++) {
        int r = fr + 8 * i;
        float4 v = *(const float4*)(Qg + (size_t)(q0 + r) * DMODEL + h * HDIM + fc);
        v.x *= SCALE; v.y *= SCALE; v.z *= SCALE; v.w *= SCALE;
        *(float4*)&Qs[r * QS_STRIDE + fc] = v;
    }
    if (tid < 64) { ms[tid] = -INFINITY; ls[tid] = 0.f; }

    float acc[4][8];
#pragma unroll
    for (int i = 0; i < 4; i++)
#pragma unroll
        for (int j = 0; j < 8; j++) acc[i][j] = 0.f;

    for (int kt = 0; kt < 64; kt++) {
        const int k0 = kt * 64;
        __syncthreads();   // previous PV consumers done before overwrite
#pragma unroll
        for (int i = 0; i < 8; i++) {
            int r = fr + 8 * i;
            *(float4*)&Ks[r * QS_STRIDE + fc] =
                *(const float4*)(Kg + (size_t)(k0 + r) * NKVD + kvh * HDIM + fc);
            *(float4*)&Vs[r * 128 + fc] =
                *(const float4*)(Vg + (size_t)(k0 + r) * NKVD + kvh * HDIM + fc);
        }
        __syncthreads();

        // ---- scores: S = Q @ K^T (scale folded into Q) ----
        float s[4][4];
#pragma unroll
        for (int i = 0; i < 4; i++)
#pragma unroll
            for (int j = 0; j < 4; j++) s[i][j] = 0.f;

#pragma unroll
        for (int kc = 0; kc < 128; kc += 4) {
            float qa[4][4], ka[4][4];
#pragma unroll
            for (int i = 0; i < 4; i++)
                *(float4*)qa[i] = *(float4*)&Qs[(sr0 + i) * QS_STRIDE + kc];
#pragma unroll
            for (int j = 0; j < 4; j++)
                *(float4*)ka[j] = *(float4*)&Ks[(sc0 + j) * QS_STRIDE + kc];
#pragma unroll
            for (int i = 0; i < 4; i++)
#pragma unroll
                for (int j = 0; j < 4; j++)
#pragma unroll
                    for (int kk = 0; kk < 4; kk++)
                        s[i][j] += qa[i][kk] * ka[j][kk];
        }
#pragma unroll
        for (int i = 0; i < 4; i++)
            *(float4*)&Ps[(sr0 + i) * PS_STRIDE + sc0] =
                make_float4(s[i][0], s[i][1], s[i][2], s[i][3]);
        __syncthreads();

        // ---- online softmax: 4 threads per row ----
        float pv[16];
        float mloc = -INFINITY;
#pragma unroll
        for (int i = 0; i < 16; i++) {
            pv[i] = Ps[srow * PS_STRIDE + sseg + i];
            mloc = fmaxf(mloc, pv[i]);
        }
        mloc = fmaxf(mloc, __shfl_xor_sync(0xffffffffu, mloc, 1));
        mloc = fmaxf(mloc, __shfl_xor_sync(0xffffffffu, mloc, 2));
        float mold = ms[srow];
        float mnew = fmaxf(mold, mloc);
        float sum = 0.f;
#pragma unroll
        for (int i = 0; i < 16; i++) {
            float e = __expf(pv[i] - mnew);
            Ps[srow * PS_STRIDE + sseg + i] = e;
            sum += e;
        }
        sum += __shfl_xor_sync(0xffffffffu, sum, 1);
        sum += __shfl_xor_sync(0xffffffffu, sum, 2);
        if ((tid & 3) == 0) {
            float a = __expf(mold - mnew);      // 0 on first tile (mold = -inf)
            als[srow] = a;
            ms[srow] = mnew;
            ls[srow] = ls[srow] * a + sum;
        }
        __syncthreads();

        // ---- rescale accumulators, then O += P @ V ----
#pragma unroll
        for (int i = 0; i < 4; i++) {
            float a = als[pr0 + i];
#pragma unroll
            for (int j = 0; j < 8; j++) acc[i][j] *= a;
        }
#pragma unroll
        for (int kc = 0; kc < 64; kc += 4) {
            float pr[4][4];
#pragma unroll
            for (int i = 0; i < 4; i++)
                *(float4*)pr[i] = *(float4*)&Ps[(pr0 + i) * PS_STRIDE + kc];
#pragma unroll
            for (int kk = 0; kk < 4; kk++) {
                float va[8];
                *(float4*)&va[0] = *(float4*)&Vs[(kc + kk) * 128 + pc0];
                *(float4*)&va[4] = *(float4*)&Vs[(kc + kk) * 128 + pc0 + 4];
#pragma unroll
                for (int i = 0; i < 4; i++) {
                    float pw = pr[i][kk];
#pragma unroll
                    for (int j = 0; j < 8; j++) acc[i][j] += pw * va[j];
                }
            }
        }
    }

    // ---- finalize: divide by l, write out ----
#pragma unroll
    for (int i = 0; i < 4; i++) {
        float inv = 1.f / ls[pr0 + i];
        float4 o0 = make_float4(acc[i][0] * inv, acc[i][1] * inv,
                                acc[i][2] * inv, acc[i][3] * inv);
        float4 o1 = make_float4(acc[i][4] * inv, acc[i][5] * inv,
                                acc[i][6] * inv, acc[i][7] * inv);
        float* orow = Og + (size_t)(q0 + pr0 + i) * DMODEL + h * HDIM + pc0;
        *(float4*)(orow)     = o0;
        *(float4*)(orow + 4) = o1;
    }
}

// ----------------------------------------------------------------------------
// launch
// ----------------------------------------------------------------------------
extern "C" void kernel_launch(void* const* d_in, const int* in_sizes, int n_in,
                              void* d_out, int out_size) {
    (void)in_sizes; (void)n_in; (void)out_size;
    const float* X  = (const float*)d_in[0];
    const float* Wq = (const float*)d_in[1];
    const float* Wk = (const float*)d_in[2];
    const float* Wv = (const float*)d_in[3];
    const float* Wo = (const float*)d_in[4];
    float* out = (float*)d_out;

    float *Qp, *Kp, *Vp, *AOp;
    cudaGetSymbolAddress((void**)&Qp, g_Q);
    cudaGetSymbolAddress((void**)&Kp, g_K);
    cudaGetSymbolAddress((void**)&Vp, g_V);
    cudaGetSymbolAddress((void**)&AOp, g_AO);

    const int smem_bytes = ATTN_SMEM_FLOATS * 4;
    cudaFuncSetAttribute(attn_kernel,
                         cudaFuncAttributeMaxDynamicSharedMemorySize, smem_bytes);

    // QKV projections
    sgemm128<<<dim3(DMODEL / 128, SEQ / 128), 256>>>(X, Wq, Qp, SEQ, DMODEL, DMODEL);
    sgemm128<<<dim3(NKVD / 128, SEQ / 128), 256>>>(X, Wk, Kp, SEQ, NKVD, DMODEL);
    sgemm128<<<dim3(NKVD / 128, SEQ / 128), 256>>>(X, Wv, Vp, SEQ, NKVD, DMODEL);

    // RoPE
    rope_table_kernel<<<(SEQ * 64 + 255) / 256, 256>>>();
    rope_apply_kernel<<<SEQ, 256>>>();

    // Attention
    attn_kernel<<<dim3(SEQ / 64, NHEAD), 256, smem_bytes>>>(Qp, Kp, Vp, AOp);

    // Output projection
    sgemm128<<<dim3(DMODEL / 128, SEQ / 128), 256>>>(AOp, Wo, out, SEQ, DMODEL, DMODEL);
}

// round 2
// speedup vs baseline: 2.9159x; 2.9159x over previous
#include <cuda_runtime.h>
#include <math.h>
#include <stdint.h>

// Problem constants
#define SEQ    4096
#define DMODEL 2048
#define NHEAD  16
#define NKV    4
#define HDIM   128
#define NKVD   512
#define SCALE  0.08838834764831845f   // 1/sqrt(128)

// Scratch (device globals; no allocation allowed)
__device__ float g_Q[SEQ * DMODEL];
__device__ float g_K[SEQ * NKVD];
__device__ float g_V[SEQ * NKVD];
__device__ float g_AO[SEQ * DMODEL];
__device__ float g_cos[SEQ * 64];
__device__ float g_sin[SEQ * 64];

// ----------------------------------------------------------------------------
// helpers
// ----------------------------------------------------------------------------
__device__ __forceinline__ float f2tf(float x) {
    float y;
    asm("cvt.rna.tf32.f32 %0, %1;" : "=f"(y) : "f"(x));
    return y;
}

__device__ __forceinline__ void mma_tf32(float c[4], const uint32_t a[4], const uint32_t b[2]) {
    asm volatile(
        "mma.sync.aligned.m16n8k8.row.col.f32.tf32.tf32.f32 "
        "{%0,%1,%2,%3}, {%4,%5,%6,%7}, {%8,%9}, {%0,%1,%2,%3};\n"
        : "+f"(c[0]), "+f"(c[1]), "+f"(c[2]), "+f"(c[3])
        : "r"(a[0]), "r"(a[1]), "r"(a[2]), "r"(a[3]), "r"(b[0]), "r"(b[1]));
}

// ----------------------------------------------------------------------------
// TF32 GEMM: C[M,N] = A[M,K] @ B[K,N], row-major. Block 128x128, BK=32.
// 8 warps in 4(m) x 2(n); warp tile 32x64 (2 m16 x 8 n8 mma tiles).
// Shared strides 36 / 136 chosen so every mma-fragment LDS is bank-conflict-free:
//   As a0 bank = (36r+c)%32 = 4*(lane/4) + lane%4 -> 0..31 unique
//   Bs b0 bank = (136k+n)%32 = 8*(lane%4) + lane/4 -> 0..31 unique
// ----------------------------------------------------------------------------
__global__ __launch_bounds__(256) void gemm_tf32(const float* __restrict__ A,
                                                 const float* __restrict__ B,
                                                 float* __restrict__ C,
                                                 int M, int N, int K) {
    __shared__ float As[128][36];
    __shared__ float Bs[32][136];

    const int tid  = threadIdx.x;
    const int wid  = tid >> 5;
    const int lane = tid & 31;
    const int gr   = lane >> 2;     // group row 0..7
    const int qc   = lane & 3;      // quad col 0..3
    const int bm = blockIdx.y * 128;
    const int bn = blockIdx.x * 128;
    const int wm = (wid & 3) * 32;  // warp m offset
    const int wn = (wid >> 2) * 64; // warp n offset

    // global-load mapping
    const int ar = tid >> 3;            // 0..31 (A rows, 4 passes of 32)
    const int ac = (tid & 7) * 4;       // 0..28 (A k cols)
    const int br = tid >> 5;            // 0..7  (B k rows, 4 passes of 8)
    const int bc = (tid & 31) * 4;      // 0..124

    float acc[2][8][4];
#pragma unroll
    for (int mt = 0; mt < 2; mt++)
#pragma unroll
        for (int nt = 0; nt < 8; nt++)
#pragma unroll
            for (int i = 0; i < 4; i++) acc[mt][nt][i] = 0.f;

    for (int k0 = 0; k0 < K; k0 += 32) {
        float4 av[4], bv[4];
#pragma unroll
        for (int i = 0; i < 4; i++)
            av[i] = *(const float4*)(A + (size_t)(bm + ar + 32 * i) * K + k0 + ac);
#pragma unroll
        for (int i = 0; i < 4; i++)
            bv[i] = *(const float4*)(B + (size_t)(k0 + br + 8 * i) * N + bn + bc);

        __syncthreads();
#pragma unroll
        for (int i = 0; i < 4; i++) {
            *(float4*)&As[ar + 32 * i][ac] =
                make_float4(f2tf(av[i].x), f2tf(av[i].y), f2tf(av[i].z), f2tf(av[i].w));
            *(float4*)&Bs[br + 8 * i][bc] =
                make_float4(f2tf(bv[i].x), f2tf(bv[i].y), f2tf(bv[i].z), f2tf(bv[i].w));
        }
        __syncthreads();

#pragma unroll
        for (int kk = 0; kk < 4; kk++) {
            const int c0 = kk * 8 + qc;
            uint32_t a[2][4], b[8][2];
#pragma unroll
            for (int mt = 0; mt < 2; mt++) {
                int r = wm + mt * 16 + gr;
                a[mt][0] = __float_as_uint(As[r][c0]);
                a[mt][1] = __float_as_uint(As[r + 8][c0]);
                a[mt][2] = __float_as_uint(As[r][c0 + 4]);
                a[mt][3] = __float_as_uint(As[r + 8][c0 + 4]);
            }
#pragma unroll
            for (int nt = 0; nt < 8; nt++) {
                int n = wn + nt * 8 + gr;
                b[nt][0] = __float_as_uint(Bs[kk * 8 + qc][n]);
                b[nt][1] = __float_as_uint(Bs[kk * 8 + qc + 4][n]);
            }
#pragma unroll
            for (int mt = 0; mt < 2; mt++)
#pragma unroll
                for (int nt = 0; nt < 8; nt++)
                    mma_tf32(acc[mt][nt], a[mt], b[nt]);
        }
    }

#pragma unroll
    for (int mt = 0; mt < 2; mt++) {
        int r = bm + wm + mt * 16 + gr;
#pragma unroll
        for (int nt = 0; nt < 8; nt++) {
            int c = bn + wn + nt * 8 + 2 * qc;
            *(float2*)(C + (size_t)r * N + c)       = make_float2(acc[mt][nt][0], acc[mt][nt][1]);
            *(float2*)(C + (size_t)(r + 8) * N + c) = make_float2(acc[mt][nt][2], acc[mt][nt][3]);
        }
    }
}

// ----------------------------------------------------------------------------
// RoPE table (double precision angles)
// ----------------------------------------------------------------------------
__global__ void rope_table_kernel() {
    int idx = blockIdx.x * blockDim.x + threadIdx.x;
    if (idx >= SEQ * 64) return;
    int pos = idx >> 6;
    int d = idx & 63;
    double inv = exp(-(double)d * (log(10000.0) / 64.0));
    double ang = (double)pos * inv;
    double s, c;
    sincos(ang, &s, &c);
    g_cos[idx] = (float)c;
    g_sin[idx] = (float)s;
}

__global__ __launch_bounds__(256) void rope_apply_kernel() {
    int pos = blockIdx.x;
    int tid = threadIdx.x;
    const float* ct = g_cos + pos * 64;
    const float* st = g_sin + pos * 64;

    float* qrow = g_Q + (size_t)pos * DMODEL;
#pragma unroll
    for (int it = 0; it < 4; it++) {
        int p = tid + it * 256;
        int head = p >> 6, d = p & 63;
        float c = ct[d], s = st[d];
        float* base = qrow + head * HDIM;
        float xr = base[d], xi = base[d + 64];
        base[d]      = xr * c - xi * s;
        base[d + 64] = xr * s + xi * c;
    }
    {
        int p = tid;
        int head = p >> 6, d = p & 63;
        float c = ct[d], s = st[d];
        float* base = g_K + (size_t)pos * NKVD + head * HDIM;
        float xr = base[d], xi = base[d + 64];
        base[d]      = xr * c - xi * s;
        base[d + 64] = xr * s + xi * c;
    }
}

// ----------------------------------------------------------------------------
// Flash attention with TF32 mma. Block = 64 q x 1 head, 256 threads (8 warps).
// Shared strides: Q/K/V 132, P 68 -> all mma LDS patterns hit 32 distinct banks.
// ----------------------------------------------------------------------------
#define QKV_STRIDE 132
#define PS_STRIDE  68
#define ATTN_SMEM_FLOATS (3 * 64 * QKV_STRIDE + 64 * PS_STRIDE + 192)

__global__ __launch_bounds__(256) void attn_kernel(const float* __restrict__ Qg,
                                                   const float* __restrict__ Kg,
                                                   const float* __restrict__ Vg,
                                                   float* __restrict__ Og) {
    extern __shared__ float sm[];
    float* Qs = sm;                            // [64][132]
    float* Ks = Qs + 64 * QKV_STRIDE;          // [64][132]
    float* Vs = Ks + 64 * QKV_STRIDE;          // [64][132]
    float* Ps = Vs + 64 * QKV_STRIDE;          // [64][68]
    float* ms = Ps + 64 * PS_STRIDE;           // [64]
    float* ls = ms + 64;                       // [64]
    float* als = ls + 64;                      // [64]

    const int tid  = threadIdx.x;
    const int wid  = tid >> 5;
    const int lane = tid & 31;
    const int gr   = lane >> 2;
    const int qc   = lane & 3;
    const int q0 = blockIdx.x * 64;
    const int h  = blockIdx.y;
    const int kvh = h >> 2;

    // warp tiles
    const int wm16 = (wid & 3) * 16;     // score & PV row base
    const int wn32 = (wid >> 2) * 32;    // score col base (4 n-tiles)
    const int wn64 = (wid >> 2) * 64;    // PV col base (8 n-tiles)

    // tile global-load mapping: 8 rows x 32 float4 cols, 8 passes
    const int fr = tid >> 5;
    const int fc = (tid & 31) * 4;

    // softmax mapping: quad of threads per row
    const int srow = tid >> 2;
    const int sseg = (tid & 3) * 16;

    // Load Q tile (scaled, tf32-rounded)
#pragma unroll
    for (int i = 0; i < 8; i++) {
        int r = fr + 8 * i;
        float4 v = *(const float4*)(Qg + (size_t)(q0 + r) * DMODEL + h * HDIM + fc);
        *(float4*)&Qs[r * QKV_STRIDE + fc] =
            make_float4(f2tf(v.x * SCALE), f2tf(v.y * SCALE), f2tf(v.z * SCALE), f2tf(v.w * SCALE));
    }
    if (tid < 64) { ms[tid] = -INFINITY; ls[tid] = 0.f; }

    float o[8][4];
#pragma unroll
    for (int nt = 0; nt < 8; nt++)
#pragma unroll
        for (int i = 0; i < 4; i++) o[nt][i] = 0.f;

    for (int kt = 0; kt < 64; kt++) {
        const int k0 = kt * 64;
        __syncthreads();   // previous-iteration consumers done
#pragma unroll
        for (int i = 0; i < 8; i++) {
            int r = fr + 8 * i;
            float4 kv = *(const float4*)(Kg + (size_t)(k0 + r) * NKVD + kvh * HDIM + fc);
            float4 vv = *(const float4*)(Vg + (size_t)(k0 + r) * NKVD + kvh * HDIM + fc);
            *(float4*)&Ks[r * QKV_STRIDE + fc] =
                make_float4(f2tf(kv.x), f2tf(kv.y), f2tf(kv.z), f2tf(kv.w));
            *(float4*)&Vs[r * QKV_STRIDE + fc] =
                make_float4(f2tf(vv.x), f2tf(vv.y), f2tf(vv.z), f2tf(vv.w));
        }
        __syncthreads();

        // ---- scores: S = Q @ K^T via mma (warp: 16 rows x 32 cols) ----
        float s[4][4];
#pragma unroll
        for (int nt = 0; nt < 4; nt++)
#pragma unroll
            for (int i = 0; i < 4; i++) s[nt][i] = 0.f;

#pragma unroll
        for (int kk = 0; kk < 16; kk++) {
            const int c0 = kk * 8 + qc;
            uint32_t a[4], b[4][2];
            int r = wm16 + gr;
            a[0] = __float_as_uint(Qs[r * QKV_STRIDE + c0]);
            a[1] = __float_as_uint(Qs[(r + 8) * QKV_STRIDE + c0]);
            a[2] = __float_as_uint(Qs[r * QKV_STRIDE + c0 + 4]);
            a[3] = __float_as_uint(Qs[(r + 8) * QKV_STRIDE + c0 + 4]);
#pragma unroll
            for (int nt = 0; nt < 4; nt++) {
                int n = wn32 + nt * 8 + gr;
                b[nt][0] = __float_as_uint(Ks[n * QKV_STRIDE + c0]);
                b[nt][1] = __float_as_uint(Ks[n * QKV_STRIDE + c0 + 4]);
            }
#pragma unroll
            for (int nt = 0; nt < 4; nt++)
                mma_tf32(s[nt], a, b[nt]);
        }
        {
            int r = wm16 + gr;
#pragma unroll
            for (int nt = 0; nt < 4; nt++) {
                int c = wn32 + nt * 8 + 2 * qc;
                *(float2*)&Ps[r * PS_STRIDE + c]       = make_float2(s[nt][0], s[nt][1]);
                *(float2*)&Ps[(r + 8) * PS_STRIDE + c] = make_float2(s[nt][2], s[nt][3]);
            }
        }
        __syncthreads();

        // ---- online softmax (4 threads per row, exact fp32 stats) ----
        float pv[16];
        float mloc = -INFINITY;
#pragma unroll
        for (int i = 0; i < 16; i++) {
            pv[i] = Ps[srow * PS_STRIDE + sseg + i];
            mloc = fmaxf(mloc, pv[i]);
        }
        mloc = fmaxf(mloc, __shfl_xor_sync(0xffffffffu, mloc, 1));
        mloc = fmaxf(mloc, __shfl_xor_sync(0xffffffffu, mloc, 2));
        float mold = ms[srow];
        float mnew = fmaxf(mold, mloc);
        float sum = 0.f;
#pragma unroll
        for (int i = 0; i < 16; i++) {
            float e = __expf(pv[i] - mnew);
            Ps[srow * PS_STRIDE + sseg + i] = f2tf(e);
            sum += e;
        }
        sum += __shfl_xor_sync(0xffffffffu, sum, 1);
        sum += __shfl_xor_sync(0xffffffffu, sum, 2);
        if ((tid & 3) == 0) {
            float a = __expf(mold - mnew);
            als[srow] = a;
            ms[srow] = mnew;
            ls[srow] = ls[srow] * a + sum;
        }
        __syncthreads();

        // ---- rescale accumulators, then O += P @ V via mma ----
        {
            float a_lo = als[wm16 + gr];
            float a_hi = als[wm16 + gr + 8];
#pragma unroll
            for (int nt = 0; nt < 8; nt++) {
                o[nt][0] *= a_lo; o[nt][1] *= a_lo;
                o[nt][2] *= a_hi; o[nt][3] *= a_hi;
            }
        }
#pragma unroll
        for (int kk = 0; kk < 8; kk++) {
            const int c0 = kk * 8 + qc;
            uint32_t a[4], b[8][2];
            int r = wm16 + gr;
            a[0] = __float_as_uint(Ps[r * PS_STRIDE + c0]);
            a[1] = __float_as_uint(Ps[(r + 8) * PS_STRIDE + c0]);
            a[2] = __float_as_uint(Ps[r * PS_STRIDE + c0 + 4]);
            a[3] = __float_as_uint(Ps[(r + 8) * PS_STRIDE + c0 + 4]);
#pragma unroll
            for (int nt = 0; nt < 8; nt++) {
                int n = wn64 + nt * 8 + gr;
                b[nt][0] = __float_as_uint(Vs[c0 * QKV_STRIDE + n]);
                b[nt][1] = __float_as_uint(Vs[(c0 + 4) * QKV_STRIDE + n]);
            }
#pragma unroll
            for (int nt = 0; nt < 8; nt++)
                mma_tf32(o[nt], a, b[nt]);
        }
    }

    // ---- finalize ----
    {
        int r = wm16 + gr;
        float inv_lo = 1.f / ls[r];
        float inv_hi = 1.f / ls[r + 8];
#pragma unroll
        for (int nt = 0; nt < 8; nt++) {
            int c = wn64 + nt * 8 + 2 * qc;
            float* o0 = Og + (size_t)(q0 + r) * DMODEL + h * HDIM + c;
            float* o1 = Og + (size_t)(q0 + r + 8) * DMODEL + h * HDIM + c;
            *(float2*)o0 = make_float2(o[nt][0] * inv_lo, o[nt][1] * inv_lo);
            *(float2*)o1 = make_float2(o[nt][2] * inv_hi, o[nt][3] * inv_hi);
        }
    }
}

// ----------------------------------------------------------------------------
// launch
// ----------------------------------------------------------------------------
extern "C" void kernel_launch(void* const* d_in, const int* in_sizes, int n_in,
                              void* d_out, int out_size) {
    (void)in_sizes; (void)n_in; (void)out_size;
    const float* X  = (const float*)d_in[0];
    const float* Wq = (const float*)d_in[1];
    const float* Wk = (const float*)d_in[2];
    const float* Wv = (const float*)d_in[3];
    const float* Wo = (const float*)d_in[4];
    float* out = (float*)d_out;

    float *Qp, *Kp, *Vp, *AOp;
    cudaGetSymbolAddress((void**)&Qp, g_Q);
    cudaGetSymbolAddress((void**)&Kp, g_K);
    cudaGetSymbolAddress((void**)&Vp, g_V);
    cudaGetSymbolAddress((void**)&AOp, g_AO);

    const int smem_bytes = ATTN_SMEM_FLOATS * 4;
    cudaFuncSetAttribute(attn_kernel,
                         cudaFuncAttributeMaxDynamicSharedMemorySize, smem_bytes);

    // QKV projections (TF32 tensor path)
    gemm_tf32<<<dim3(DMODEL / 128, SEQ / 128), 256>>>(X, Wq, Qp, SEQ, DMODEL, DMODEL);
    gemm_tf32<<<dim3(NKVD / 128, SEQ / 128), 256>>>(X, Wk, Kp, SEQ, NKVD, DMODEL);
    gemm_tf32<<<dim3(NKVD / 128, SEQ / 128), 256>>>(X, Wv, Vp, SEQ, NKVD, DMODEL);

    // RoPE
    rope_table_kernel<<<(SEQ * 64 + 255) / 256, 256>>>();
    rope_apply_kernel<<<SEQ, 256>>>();

    // Attention
    attn_kernel<<<dim3(SEQ / 64, NHEAD), 256, smem_bytes>>>(Qp, Kp, Vp, AOp);

    // Output projection
    gemm_tf32<<<dim3(DMODEL / 128, SEQ / 128), 256>>>(AOp, Wo, out, SEQ, DMODEL, DMODEL);
}

// round 4
// speedup vs baseline: 5.6653x; 1.9429x over previous
#include <cuda_runtime.h>
#include <cuda_fp16.h>
#include <math.h>
#include <stdint.h>

// Problem constants
#define SEQ    4096
#define DMODEL 2048
#define NHEAD  16
#define NKV    4
#define HDIM   128
#define NQKV   3072      // fused Q|K|V output columns
#define SCALE  0.08838834764831845f   // 1/sqrt(128)

// ---------------------------------------------------------------------------
// Scratch (device globals; no allocation allowed)
// ---------------------------------------------------------------------------
__device__ float  g_QKV[SEQ * NQKV];        // fused Q|K|V fp32, row stride 3072
__device__ float  g_AO[SEQ * DMODEL];       // attention output fp32
__device__ __half g_Wt[NQKV * DMODEL];      // fused Wq|Wk|Wv transposed [N,K] fp16
__device__ __half g_Wot[DMODEL * DMODEL];   // Wo transposed [N,K] fp16

// ---------------------------------------------------------------------------
// mma helper: m16n8k16 fp16 inputs, fp32 accumulate
// ---------------------------------------------------------------------------
__device__ __forceinline__ void mma_f16(float c[4], const uint32_t a[4], const uint32_t b[2]) {
    asm volatile(
        "mma.sync.aligned.m16n8k16.row.col.f32.f16.f16.f32 "
        "{%0,%1,%2,%3}, {%4,%5,%6,%7}, {%8,%9}, {%0,%1,%2,%3};\n"
        : "+f"(c[0]), "+f"(c[1]), "+f"(c[2]), "+f"(c[3])
        : "r"(a[0]), "r"(a[1]), "r"(a[2]), "r"(a[3]), "r"(b[0]), "r"(b[1]));
}

__device__ __forceinline__ uint32_t pack_h2(float x, float y) {
    __half2 h = __floats2half2_rn(x, y);
    return *(uint32_t*)&h;
}

// ---------------------------------------------------------------------------
// W [K,N] fp32 row-major -> T [N,K] fp16
// ---------------------------------------------------------------------------
__global__ __launch_bounds__(256) void transpose_f16(const float* __restrict__ W,
                                                     __half* __restrict__ T,
                                                     int K, int N) {
    __shared__ float t[32][33];
    int tx = threadIdx.x, ty = threadIdx.y;
    int n0 = blockIdx.x * 32, k0 = blockIdx.y * 32;
#pragma unroll
    for (int i = 0; i < 4; i++)
        t[ty + 8 * i][tx] = W[(size_t)(k0 + ty + 8 * i) * N + n0 + tx];
    __syncthreads();
#pragma unroll
    for (int i = 0; i < 4; i++)
        T[(size_t)(n0 + ty + 8 * i) * K + k0 + tx] = __float2half(t[tx][ty + 8 * i]);
}

// ---------------------------------------------------------------------------
// fp16 GEMM: C[M,N] = A[M,K](fp32) @ Bt[N,K](fp16)^T.  Block 128x128, BK=32,
// 8 warps (4m x 2n), warp tile 32x64, double-buffered smem, 1 sync per chunk.
// Stride 40 halfs => all fragment LDS conflict-free: bank = (20r+qc)%32.
// ---------------------------------------------------------------------------
#define GST 40
__global__ __launch_bounds__(256) void gemm_f16(const float* __restrict__ A,
                                                const __half* __restrict__ Bt,
                                                float* __restrict__ C,
                                                int N, int K) {
    __shared__ __half As[2][128 * GST];
    __shared__ __half Bs[2][128 * GST];

    const int tid  = threadIdx.x;
    const int wid  = tid >> 5;
    const int lane = tid & 31;
    const int gr   = lane >> 2;
    const int qc   = lane & 3;
    const int bm = blockIdx.y * 128;
    const int bn = blockIdx.x * 128;
    const int wm = (wid & 3) * 32;
    const int wn = (wid >> 2) * 64;

    const int lr = tid >> 1;          // 0..127
    const int lk = (tid & 1) * 16;    // 0 or 16

    float acc[2][8][4];
#pragma unroll
    for (int mt = 0; mt < 2; mt++)
#pragma unroll
        for (int nt = 0; nt < 8; nt++)
#pragma unroll
            for (int i = 0; i < 4; i++) acc[mt][nt][i] = 0.f;

    const int T = K >> 5;
    float4 va[4];
    uint4  vb[2];

    // prologue: load + store chunk 0
#pragma unroll
    for (int j = 0; j < 4; j++)
        va[j] = *(const float4*)(A + (size_t)(bm + lr) * K + lk + 4 * j);
#pragma unroll
    for (int j = 0; j < 2; j++)
        vb[j] = *(const uint4*)(Bt + (size_t)(bn + lr) * K + lk + 8 * j);
#pragma unroll
    for (int j = 0; j < 4; j++) {
        uint2 p;
        p.x = pack_h2(va[j].x, va[j].y);
        p.y = pack_h2(va[j].z, va[j].w);
        *(uint2*)&As[0][lr * GST + lk + 4 * j] = p;
    }
#pragma unroll
    for (int j = 0; j < 2; j++)
        *(uint4*)&Bs[0][lr * GST + lk + 8 * j] = vb[j];
    __syncthreads();

    for (int t = 0; t < T; t++) {
        const int buf = t & 1;
        if (t + 1 < T) {
            int k0 = (t + 1) * 32;
#pragma unroll
            for (int j = 0; j < 4; j++)
                va[j] = *(const float4*)(A + (size_t)(bm + lr) * K + k0 + lk + 4 * j);
#pragma unroll
            for (int j = 0; j < 2; j++)
                vb[j] = *(const uint4*)(Bt + (size_t)(bn + lr) * K + k0 + lk + 8 * j);
        }

        // compute from buf
#pragma unroll
        for (int kk = 0; kk < 2; kk++) {
            uint32_t a[2][4], b[8][2];
#pragma unroll
            for (int mt = 0; mt < 2; mt++) {
                int r = wm + mt * 16 + gr;
                a[mt][0] = *(uint32_t*)&As[buf][r * GST + kk * 16 + 2 * qc];
                a[mt][1] = *(uint32_t*)&As[buf][(r + 8) * GST + kk * 16 + 2 * qc];
                a[mt][2] = *(uint32_t*)&As[buf][r * GST + kk * 16 + 2 * qc + 8];
                a[mt][3] = *(uint32_t*)&As[buf][(r + 8) * GST + kk * 16 + 2 * qc + 8];
            }
#pragma unroll
            for (int nt = 0; nt < 8; nt++) {
                int n = wn + nt * 8 + gr;
                b[nt][0] = *(uint32_t*)&Bs[buf][n * GST + kk * 16 + 2 * qc];
                b[nt][1] = *(uint32_t*)&Bs[buf][n * GST + kk * 16 + 2 * qc + 8];
            }
#pragma unroll
            for (int mt = 0; mt < 2; mt++)
#pragma unroll
                for (int nt = 0; nt < 8; nt++)
                    mma_f16(acc[mt][nt], a[mt], b[nt]);
        }

        if (t + 1 < T) {
            const int nbuf = (t + 1) & 1;
#pragma unroll
            for (int j = 0; j < 4; j++) {
                uint2 p;
                p.x = pack_h2(va[j].x, va[j].y);
                p.y = pack_h2(va[j].z, va[j].w);
                *(uint2*)&As[nbuf][lr * GST + lk + 4 * j] = p;
            }
#pragma unroll
            for (int j = 0; j < 2; j++)
                *(uint4*)&Bs[nbuf][lr * GST + lk + 8 * j] = vb[j];
            __syncthreads();
        }
    }

#pragma unroll
    for (int mt = 0; mt < 2; mt++) {
        int r = bm + wm + mt * 16 + gr;
#pragma unroll
        for (int nt = 0; nt < 8; nt++) {
            int c = bn + wn + nt * 8 + 2 * qc;
            *(float2*)(C + (size_t)r * N + c)       = make_float2(acc[mt][nt][0], acc[mt][nt][1]);
            *(float2*)(C + (size_t)(r + 8) * N + c) = make_float2(acc[mt][nt][2], acc[mt][nt][3]);
        }
    }
}

// ---------------------------------------------------------------------------
// RoPE in place on fused QKV fp32 buffer (row stride 3072)
// ---------------------------------------------------------------------------
__global__ __launch_bounds__(256) void rope_kernel(float* __restrict__ qkv) {
    __shared__ float cs[64], sn[64];
    int pos = blockIdx.x;
    int tid = threadIdx.x;
    if (tid < 64) {
        double inv = exp(-(double)tid * (log(10000.0) / 64.0));
        double s, c;
        sincos((double)pos * inv, &s, &c);
        cs[tid] = (float)c;
        sn[tid] = (float)s;
    }
    __syncthreads();
    float* row = qkv + (size_t)pos * NQKV;
#pragma unroll
    for (int it = 0; it < 4; it++) {          // Q: 1024 pairs
        int p = tid + it * 256;
        int head = p >> 6, d = p & 63;
        float c = cs[d], s = sn[d];
        float* base = row + head * HDIM;
        float xr = base[d], xi = base[d + 64];
        base[d]      = xr * c - xi * s;
        base[d + 64] = xr * s + xi * c;
    }
    {                                          // K: 256 pairs
        int head = tid >> 6, d = tid & 63;
        float c = cs[d], s = sn[d];
        float* base = row + 2048 + head * HDIM;
        float xr = base[d], xi = base[d + 64];
        base[d]      = xr * c - xi * s;
        base[d + 64] = xr * s + xi * c;
    }
}

// ---------------------------------------------------------------------------
// Flash attention, fp16 mma. Block = 64 q x 1 head, 256 threads (8 warps).
// Q/K/V tiles fp16 stride 136 halfs; P fp16 stride 72 halfs.
// V consumed via ldmatrix.x4.trans (conflict-free: 272B row = 17 x 16B).
// ---------------------------------------------------------------------------
#define AQS 136
#define APS 72
#define ATTN_SMEM_BYTES ((3 * 64 * AQS + 64 * APS) * 2 + 3 * 64 * 4)

__global__ __launch_bounds__(256) void attn_kernel(const float* __restrict__ Qg,
                                                   const float* __restrict__ Kg,
                                                   const float* __restrict__ Vg,
                                                   float* __restrict__ Og, int ld) {
    extern __shared__ __half smh[];
    __half* Qs = smh;                       // [64][136]
    __half* Ks = Qs + 64 * AQS;             // [64][136]
    __half* Vs = Ks + 64 * AQS;             // [64][136]  natural [s][d]
    __half* Ps = Vs + 64 * AQS;             // [64][72]
    float*  ms  = (float*)(Ps + 64 * APS);  // [64]
    float*  ls  = ms + 64;
    float*  als = ls + 64;

    const int tid  = threadIdx.x;
    const int wid  = tid >> 5;
    const int lane = tid & 31;
    const int gr   = lane >> 2;
    const int qc   = lane & 3;
    const int q0 = blockIdx.x * 64;
    const int h  = blockIdx.y;
    const int kvh = h >> 2;

    const int wm16 = (wid & 3) * 16;     // q-row base for this warp
    const int wn32 = (wid >> 2) * 32;    // score col base
    const int wn64 = (wid >> 2) * 64;    // PV col base
    const int fr = tid >> 5;             // tile load: warp -> row
    const int fc = (tid & 31) * 4;       // 4 floats per lane
    const int srow = tid >> 2;
    const int sseg = (tid & 3) * 16;

    const uint32_t vs_base = (uint32_t)__cvta_generic_to_shared(Vs);

    // Load Q (scaled -> fp16)
#pragma unroll
    for (int i = 0; i < 8; i++) {
        int r = fr + 8 * i;
        float4 v = *(const float4*)(Qg + (size_t)(q0 + r) * ld + h * HDIM + fc);
        uint2 p;
        p.x = pack_h2(v.x * SCALE, v.y * SCALE);
        p.y = pack_h2(v.z * SCALE, v.w * SCALE);
        *(uint2*)&Qs[r * AQS + fc] = p;
    }
    if (tid < 64) { ms[tid] = -INFINITY; ls[tid] = 0.f; }

    float o[8][4];
#pragma unroll
    for (int nt = 0; nt < 8; nt++)
#pragma unroll
        for (int i = 0; i < 4; i++) o[nt][i] = 0.f;

    for (int kt = 0; kt < 64; kt++) {
        const int k0 = kt * 64;
        __syncthreads();   // previous-iteration consumers done
#pragma unroll
        for (int i = 0; i < 8; i++) {
            int r = fr + 8 * i;
            float4 kv = *(const float4*)(Kg + (size_t)(k0 + r) * ld + kvh * HDIM + fc);
            float4 vv = *(const float4*)(Vg + (size_t)(k0 + r) * ld + kvh * HDIM + fc);
            uint2 pk, pv2;
            pk.x = pack_h2(kv.x, kv.y);  pk.y = pack_h2(kv.z, kv.w);
            pv2.x = pack_h2(vv.x, vv.y); pv2.y = pack_h2(vv.z, vv.w);
            *(uint2*)&Ks[r * AQS + fc] = pk;
            *(uint2*)&Vs[r * AQS + fc] = pv2;
        }
        __syncthreads();

        // ---- scores: S = Q @ K^T, warp tile 16q x 32k ----
        float s[4][4];
#pragma unroll
        for (int nt = 0; nt < 4; nt++)
#pragma unroll
            for (int i = 0; i < 4; i++) s[nt][i] = 0.f;

#pragma unroll
        for (int kk = 0; kk < 8; kk++) {
            uint32_t a[4], b[4][2];
            int r = wm16 + gr;
            int co = kk * 16 + 2 * qc;
            a[0] = *(uint32_t*)&Qs[r * AQS + co];
            a[1] = *(uint32_t*)&Qs[(r + 8) * AQS + co];
            a[2] = *(uint32_t*)&Qs[r * AQS + co + 8];
            a[3] = *(uint32_t*)&Qs[(r + 8) * AQS + co + 8];
#pragma unroll
            for (int nt = 0; nt < 4; nt++) {
                int n = wn32 + nt * 8 + gr;
                b[nt][0] = *(uint32_t*)&Ks[n * AQS + co];
                b[nt][1] = *(uint32_t*)&Ks[n * AQS + co + 8];
            }
#pragma unroll
            for (int nt = 0; nt < 4; nt++)
                mma_f16(s[nt], a, b[nt]);
        }
        {
            int r = wm16 + gr;
#pragma unroll
            for (int nt = 0; nt < 4; nt++) {
                int c = wn32 + nt * 8 + 2 * qc;
                *(uint32_t*)&Ps[r * APS + c]       = pack_h2(s[nt][0], s[nt][1]);
                *(uint32_t*)&Ps[(r + 8) * APS + c] = pack_h2(s[nt][2], s[nt][3]);
            }
        }
        __syncthreads();

        // ---- online softmax: 4 threads per row, fp32 stats ----
        float pv[16];
        {
            __half2* prow = (__half2*)&Ps[srow * APS + sseg];
            float mloc = -INFINITY;
#pragma unroll
            for (int j = 0; j < 8; j++) {
                float2 f = __half22float2(prow[j]);
                pv[2 * j] = f.x; pv[2 * j + 1] = f.y;
                mloc = fmaxf(mloc, fmaxf(f.x, f.y));
            }
            mloc = fmaxf(mloc, __shfl_xor_sync(0xffffffffu, mloc, 1));
            mloc = fmaxf(mloc, __shfl_xor_sync(0xffffffffu, mloc, 2));
            float mold = ms[srow];
            float mnew = fmaxf(mold, mloc);
            float sum = 0.f;
#pragma unroll
            for (int j = 0; j < 8; j++) {
                float e0 = __expf(pv[2 * j] - mnew);
                float e1 = __expf(pv[2 * j + 1] - mnew);
                prow[j] = __floats2half2_rn(e0, e1);
                sum += e0 + e1;
            }
            sum += __shfl_xor_sync(0xffffffffu, sum, 1);
            sum += __shfl_xor_sync(0xffffffffu, sum, 2);
            if ((tid & 3) == 0) {
                float a = __expf(mold - mnew);
                als[srow] = a;
                ms[srow] = mnew;
                ls[srow] = ls[srow] * a + sum;
            }
        }
        __syncthreads();

        // ---- rescale, then O += P @ V (V via ldmatrix.trans) ----
        {
            float a_lo = als[wm16 + gr];
            float a_hi = als[wm16 + gr + 8];
#pragma unroll
            for (int nt = 0; nt < 8; nt++) {
                o[nt][0] *= a_lo; o[nt][1] *= a_lo;
                o[nt][2] *= a_hi; o[nt][3] *= a_hi;
            }
        }
#pragma unroll
        for (int kk = 0; kk < 4; kk++) {
            uint32_t a[4];
            int r = wm16 + gr;
            int co = kk * 16 + 2 * qc;
            a[0] = *(uint32_t*)&Ps[r * APS + co];
            a[1] = *(uint32_t*)&Ps[(r + 8) * APS + co];
            a[2] = *(uint32_t*)&Ps[r * APS + co + 8];
            a[3] = *(uint32_t*)&Ps[(r + 8) * APS + co + 8];

            const int vrow = kk * 16 + (lane & 7) + ((lane >> 4) << 3);
#pragma unroll
            for (int nt2 = 0; nt2 < 4; nt2++) {
                int vcol = wn64 + nt2 * 16 + ((lane >> 3) & 1) * 8;
                uint32_t addr = vs_base + (uint32_t)(vrow * AQS + vcol) * 2u;
                uint32_t r0, r1, r2, r3;
                asm volatile(
                    "ldmatrix.sync.aligned.m8n8.x4.trans.shared.b16 {%0,%1,%2,%3}, [%4];"
                    : "=r"(r0), "=r"(r1), "=r"(r2), "=r"(r3) : "r"(addr));
                uint32_t b0[2] = {r0, r2};
                uint32_t b1[2] = {r1, r3};
                mma_f16(o[nt2 * 2],     a, b0);
                mma_f16(o[nt2 * 2 + 1], a, b1);
            }
        }
    }

    // ---- finalize ----
    {
        int r = wm16 + gr;
        float inv_lo = 1.f / ls[r];
        float inv_hi = 1.f / ls[r + 8];
#pragma unroll
        for (int nt = 0; nt < 8; nt++) {
            int c = wn64 + nt * 8 + 2 * qc;
            float* o0 = Og + (size_t)(q0 + r) * DMODEL + h * HDIM + c;
            float* o1 = Og + (size_t)(q0 + r + 8) * DMODEL + h * HDIM + c;
            *(float2*)o0 = make_float2(o[nt][0] * inv_lo, o[nt][1] * inv_lo);
            *(float2*)o1 = make_float2(o[nt][2] * inv_hi, o[nt][3] * inv_hi);
        }
    }
}

// ---------------------------------------------------------------------------
// launch
// ---------------------------------------------------------------------------
extern "C" void kernel_launch(void* const* d_in, const int* in_sizes, int n_in,
                              void* d_out, int out_size) {
    (void)in_sizes; (void)n_in; (void)out_size;
    const float* X  = (const float*)d_in[0];
    const float* Wq = (const float*)d_in[1];
    const float* Wk = (const float*)d_in[2];
    const float* Wv = (const float*)d_in[3];
    const float* Wo = (const float*)d_in[4];
    float* out = (float*)d_out;

    float *QKVp, *AOp;
    __half *Wt, *Wot;
    cudaGetSymbolAddress((void**)&QKVp, g_QKV);
    cudaGetSymbolAddress((void**)&AOp, g_AO);
    cudaGetSymbolAddress((void**)&Wt, g_Wt);
    cudaGetSymbolAddress((void**)&Wot, g_Wot);

    cudaFuncSetAttribute(attn_kernel, cudaFuncAttributeMaxDynamicSharedMemorySize,
                         ATTN_SMEM_BYTES);

    // 1) transpose weights to fp16 [N,K] (fused Wq|Wk|Wv, and Wo)
    transpose_f16<<<dim3(2048 / 32, 2048 / 32), dim3(32, 8)>>>(Wq, Wt, DMODEL, 2048);
    transpose_f16<<<dim3(512 / 32, 2048 / 32), dim3(32, 8)>>>(Wk, Wt + 2048 * DMODEL, DMODEL, 512);
    transpose_f16<<<dim3(512 / 32, 2048 / 32), dim3(32, 8)>>>(Wv, Wt + 2560 * DMODEL, DMODEL, 512);
    transpose_f16<<<dim3(2048 / 32, 2048 / 32), dim3(32, 8)>>>(Wo, Wot, DMODEL, 2048);

    // 2) fused QKV projection
    gemm_f16<<<dim3(NQKV / 128, SEQ / 128), 256>>>(X, Wt, QKVp, NQKV, DMODEL);

    // 3) RoPE in place
    rope_kernel<<<SEQ, 256>>>(QKVp);

    // 4) attention
    attn_kernel<<<dim3(SEQ / 64, NHEAD), 256, ATTN_SMEM_BYTES>>>(
        QKVp, QKVp + 2048, QKVp + 2560, AOp, NQKV);

    // 5) output projection
    gemm_f16<<<dim3(DMODEL / 128, SEQ / 128), 256>>>(AOp, Wot, out, DMODEL, DMODEL);
}

// round 6
// speedup vs baseline: 6.3627x; 1.1231x over previous
#include <cuda_runtime.h>
#include <cuda_fp16.h>
#include <math.h>
#include <stdint.h>

// Problem constants
#define SEQ    4096
#define DMODEL 2048
#define NHEAD  16
#define NKV    4
#define HDIM   128
#define NQKV   3072
#define SCALE  0.08838834764831845f   // 1/sqrt(128)

// ---------------------------------------------------------------------------
// Scratch (device globals; no allocation allowed)
// ---------------------------------------------------------------------------
__device__ float  g_QKV[SEQ * NQKV];          // fused Q|K|V fp32 (gemm out)
__device__ __half g_Wt[NQKV * DMODEL];        // fused Wq|Wk|Wv transposed [N,K]
__device__ __half g_Wot[DMODEL * DMODEL];     // Wo transposed [N,K]
__device__ __half g_Xhi[SEQ * DMODEL];        // X hi/lo split
__device__ __half g_Xlo[SEQ * DMODEL];
__device__ __half g_Qh[NHEAD * SEQ * HDIM];   // per-head planes, rope+scale
__device__ __half g_Kh[NKV * SEQ * HDIM];     // rope applied
__device__ __half g_Vh[NKV * SEQ * HDIM];
__device__ __half g_AOhi[SEQ * DMODEL];       // attention out hi/lo split
__device__ __half g_AOlo[SEQ * DMODEL];

// ---------------------------------------------------------------------------
// helpers
// ---------------------------------------------------------------------------
__device__ __forceinline__ void mma_f16(float c[4], const uint32_t a[4], const uint32_t b[2]) {
    asm volatile(
        "mma.sync.aligned.m16n8k16.row.col.f32.f16.f16.f32 "
        "{%0,%1,%2,%3}, {%4,%5,%6,%7}, {%8,%9}, {%0,%1,%2,%3};\n"
        : "+f"(c[0]), "+f"(c[1]), "+f"(c[2]), "+f"(c[3])
        : "r"(a[0]), "r"(a[1]), "r"(a[2]), "r"(a[3]), "r"(b[0]), "r"(b[1]));
}

__device__ __forceinline__ uint32_t pack_h2(float x, float y) {
    __half2 h = __floats2half2_rn(x, y);
    return *(uint32_t*)&h;
}

__device__ __forceinline__ void cpa16(uint32_t saddr, const void* g) {
    asm volatile("cp.async.cg.shared.global [%0], [%1], 16;" :: "r"(saddr), "l"(g));
}
#define CP_COMMIT() asm volatile("cp.async.commit_group;" ::: "memory")
#define CP_WAIT(n)  asm volatile("cp.async.wait_group %0;" :: "n"(n) : "memory")

__device__ __forceinline__ void ldsm4(uint32_t& r0, uint32_t& r1, uint32_t& r2, uint32_t& r3,
                                      uint32_t addr) {
    asm volatile("ldmatrix.sync.aligned.m8n8.x4.shared.b16 {%0,%1,%2,%3}, [%4];"
                 : "=r"(r0), "=r"(r1), "=r"(r2), "=r"(r3) : "r"(addr));
}
__device__ __forceinline__ void ldsm4t(uint32_t& r0, uint32_t& r1, uint32_t& r2, uint32_t& r3,
                                       uint32_t addr) {
    asm volatile("ldmatrix.sync.aligned.m8n8.x4.trans.shared.b16 {%0,%1,%2,%3}, [%4];"
                 : "=r"(r0), "=r"(r1), "=r"(r2), "=r"(r3) : "r"(addr));
}
__device__ __forceinline__ void stsm4(uint32_t addr, uint32_t r0, uint32_t r1,
                                      uint32_t r2, uint32_t r3) {
    asm volatile("stmatrix.sync.aligned.m8n8.x4.shared.b16 [%0], {%1,%2,%3,%4};"
                 :: "r"(addr), "r"(r0), "r"(r1), "r"(r2), "r"(r3) : "memory");
}

// ---------------------------------------------------------------------------
// prep kernels
// ---------------------------------------------------------------------------
__global__ __launch_bounds__(256) void transpose_f16(const float* __restrict__ W,
                                                     __half* __restrict__ T,
                                                     int K, int N) {
    __shared__ float t[32][33];
    int tx = threadIdx.x, ty = threadIdx.y;
    int n0 = blockIdx.x * 32, k0 = blockIdx.y * 32;
#pragma unroll
    for (int i = 0; i < 4; i++)
        t[ty + 8 * i][tx] = W[(size_t)(k0 + ty + 8 * i) * N + n0 + tx];
    __syncthreads();
#pragma unroll
    for (int i = 0; i < 4; i++)
        T[(size_t)(n0 + ty + 8 * i) * K + k0 + tx] = __float2half(t[tx][ty + 8 * i]);
}

__global__ __launch_bounds__(256) void split_x(const float* __restrict__ src,
                                               __half* __restrict__ hi,
                                               __half* __restrict__ lo, int n4) {
    int i = blockIdx.x * blockDim.x + threadIdx.x;
    if (i >= n4) return;
    float4 v = ((const float4*)src)[i];
    float f[4] = {v.x, v.y, v.z, v.w};
    __half h[4], l[4];
#pragma unroll
    for (int j = 0; j < 4; j++) {
        h[j] = __float2half(f[j]);
        l[j] = __float2half(f[j] - __half2float(h[j]));
    }
    ((uint2*)hi)[i] = *(uint2*)h;
    ((uint2*)lo)[i] = *(uint2*)l;
}

// ---------------------------------------------------------------------------
// GEMM with A hi/lo split: C[M,N] fp32 = (Ahi+Alo)[M,K]h @ Bt[N,K]h^T
// Block 128x128, BK=64, 2-stage cp.async, ldmatrix fragments. 256 thr.
// smem stride 72 halfs (144B = 9x16B): ldmatrix banks 4r%32 -> conflict-free.
// ---------------------------------------------------------------------------
#define GSS 72
#define GS_TILE  (128 * GSS)
#define GS_STAGE (3 * GS_TILE)
#define GEMM_SMEM_BYTES (2 * GS_STAGE * 2)

__global__ __launch_bounds__(256, 2) void gemm_asplit(
    const __half* __restrict__ Ahi, const __half* __restrict__ Alo,
    const __half* __restrict__ Bt, float* __restrict__ C, int N, int K) {
    extern __shared__ __half gsm[];
    const uint32_t sb = (uint32_t)__cvta_generic_to_shared(gsm);
    const int tid = threadIdx.x, wid = tid >> 5, lane = tid & 31;
    const int gr = lane >> 2, qc = lane & 3;
    const int bm = blockIdx.y * 128, bn = blockIdx.x * 128;
    const int wm = (wid & 3) * 32, wn = (wid >> 2) * 64;
    const int T = K >> 6;

    float acc[2][8][4];
#pragma unroll
    for (int mt = 0; mt < 2; mt++)
#pragma unroll
        for (int nt = 0; nt < 8; nt++)
#pragma unroll
            for (int i = 0; i < 4; i++) acc[mt][nt][i] = 0.f;

    // FIXED loader: each tile = 128 rows x 64 halfs = 1024 x 16B chunks
    // (round-5 bug: only 512 chunks/tile -> half of smem uninitialized)
    auto load_chunk = [&](int t) {
        const int k0 = t * 64;
        const uint32_t stage = (t & 1) ? (uint32_t)GS_STAGE : 0u;
#pragma unroll
        for (int tile = 0; tile < 3; tile++) {
            const __half* g = (tile == 0) ? Ahi : (tile == 1) ? Alo : Bt;
            const int gbase = (tile == 2) ? bn : bm;
#pragma unroll
            for (int i = 0; i < 4; i++) {
                int idx = tid + 256 * i;
                int r = idx >> 3, c = idx & 7;
                cpa16(sb + (stage + tile * GS_TILE + r * GSS + c * 8) * 2,
                      g + (size_t)(gbase + r) * K + k0 + c * 8);
            }
        }
    };

    load_chunk(0);
    CP_COMMIT();

    for (int t = 0; t < T; t++) {
        if (t + 1 < T) { load_chunk(t + 1); CP_COMMIT(); CP_WAIT(1); }
        else           { CP_WAIT(0); }
        __syncthreads();
        const uint32_t stage = (t & 1) ? (uint32_t)GS_STAGE : 0u;

#pragma unroll
        for (int kk = 0; kk < 4; kk++) {
            uint32_t b[8][2];
#pragma unroll
            for (int ntp = 0; ntp < 4; ntp++) {
                int row = wn + ntp * 16 + (lane & 7) + ((lane >> 4) & 1) * 8;
                int col = kk * 16 + ((lane >> 3) & 1) * 8;
                ldsm4(b[2 * ntp][0], b[2 * ntp][1], b[2 * ntp + 1][0], b[2 * ntp + 1][1],
                      sb + (stage + 2 * GS_TILE + row * GSS + col) * 2);
            }
#pragma unroll
            for (int sp = 0; sp < 2; sp++) {
                uint32_t a[2][4];
#pragma unroll
                for (int mt = 0; mt < 2; mt++) {
                    int row = wm + mt * 16 + (lane & 15);
                    int col = kk * 16 + (lane >> 4) * 8;
                    ldsm4(a[mt][0], a[mt][1], a[mt][2], a[mt][3],
                          sb + (stage + sp * GS_TILE + row * GSS + col) * 2);
                }
#pragma unroll
                for (int mt = 0; mt < 2; mt++)
#pragma unroll
                    for (int nt = 0; nt < 8; nt++)
                        mma_f16(acc[mt][nt], a[mt], b[nt]);
            }
        }
        __syncthreads();
    }

#pragma unroll
    for (int mt = 0; mt < 2; mt++) {
        int r = bm + wm + mt * 16 + gr;
#pragma unroll
        for (int nt = 0; nt < 8; nt++) {
            int c = bn + wn + nt * 8 + 2 * qc;
            *(float2*)(C + (size_t)r * N + c)       = make_float2(acc[mt][nt][0], acc[mt][nt][1]);
            *(float2*)(C + (size_t)(r + 8) * N + c) = make_float2(acc[mt][nt][2], acc[mt][nt][3]);
        }
    }
}

// ---------------------------------------------------------------------------
// RoPE + fp16 conversion into per-head planes
// ---------------------------------------------------------------------------
__global__ __launch_bounds__(256) void rope_convert(const float* __restrict__ qkv,
                                                    __half* __restrict__ Qh,
                                                    __half* __restrict__ Kh,
                                                    __half* __restrict__ Vh) {
    __shared__ float cs[64], sn[64];
    const int pos = blockIdx.x, tid = threadIdx.x;
    if (tid < 64) {
        double inv = exp(-(double)tid * (log(10000.0) / 64.0));
        double s, c;
        sincos((double)pos * inv, &s, &c);
        cs[tid] = (float)c;
        sn[tid] = (float)s;
    }
    __syncthreads();
    const float* row = qkv + (size_t)pos * NQKV;
#pragma unroll
    for (int it = 0; it < 4; it++) {            // Q: 1024 pairs, scaled
        int p = tid + it * 256;
        int head = p >> 6, d = p & 63;
        float c = cs[d], s = sn[d];
        const float* base = row + head * HDIM;
        float xr = base[d], xi = base[d + 64];
        __half* o = Qh + (size_t)head * SEQ * HDIM + (size_t)pos * HDIM;
        o[d]      = __float2half((xr * c - xi * s) * SCALE);
        o[d + 64] = __float2half((xr * s + xi * c) * SCALE);
    }
    {                                            // K: 256 pairs
        int kvh = tid >> 6, d = tid & 63;
        float c = cs[d], s = sn[d];
        const float* base = row + 2048 + kvh * HDIM;
        float xr = base[d], xi = base[d + 64];
        __half* o = Kh + (size_t)kvh * SEQ * HDIM + (size_t)pos * HDIM;
        o[d]      = __float2half(xr * c - xi * s);
        o[d + 64] = __float2half(xr * s + xi * c);
    }
#pragma unroll
    for (int j = 0; j < 2; j++) {                // V: 512 values
        int e = tid * 2 + j;
        int kvh = e >> 7, d = e & 127;
        Vh[(size_t)kvh * SEQ * HDIM + (size_t)pos * HDIM + d] =
            __float2half(row[2560 + e]);
    }
}

// ---------------------------------------------------------------------------
// Flash attention: 64q x 1 head per block, 256 thr, fp16 ldmatrix everywhere,
// cp.async double-buffered K/V. Writes AOhi/AOlo fp16 split directly.
// smem stride 136 halfs (272B = 17x16B): all LDSM patterns conflict-free.
// ---------------------------------------------------------------------------
#define AST 136
#define APS 72
#define AS_Q  0
#define AS_K  (64 * AST)          // 2 buffers
#define AS_V  (64 * AST * 3)      // 2 buffers
#define AS_P  (64 * AST * 5)
#define AS_ST (AS_P + 64 * APS)   // fp32 stats after this (half offset)
#define ATTN_SMEM_BYTES (AS_ST * 2 + 3 * 64 * 4)

__global__ __launch_bounds__(256, 2) void attn2(const __half* __restrict__ Qh,
                                                const __half* __restrict__ Kh,
                                                const __half* __restrict__ Vh,
                                                __half* __restrict__ AOhi,
                                                __half* __restrict__ AOlo) {
    extern __shared__ __half smh[];
    const uint32_t sb = (uint32_t)__cvta_generic_to_shared(smh);
    float* ms  = (float*)(smh + AS_ST);
    float* ls  = ms + 64;
    float* als = ls + 64;

    const int tid = threadIdx.x, wid = tid >> 5, lane = tid & 31;
    const int gr = lane >> 2, qc = lane & 3;
    const int q0 = blockIdx.x * 64;
    const int h  = blockIdx.y;
    const int kvh = h >> 2;
    const int wm16 = (wid & 3) * 16;
    const int wn32 = (wid >> 2) * 32;
    const int wn64 = (wid >> 2) * 64;
    const int srow = tid >> 2;
    const int sseg = (tid & 3) * 16;

    const __half* Kp = Kh + (size_t)kvh * SEQ * HDIM;
    const __half* Vp = Vh + (size_t)kvh * SEQ * HDIM;

    // prologue: Q tile + K0/V0 in one commit group
    {
        const __half* Qp = Qh + (size_t)h * SEQ * HDIM + (size_t)q0 * HDIM;
#pragma unroll
        for (int i = 0; i < 4; i++) {
            int lin = tid + 256 * i;
            int r = lin >> 4, c = lin & 15;
            cpa16(sb + (AS_Q + r * AST + c * 8) * 2, Qp + (size_t)r * HDIM + c * 8);
            cpa16(sb + (AS_K + r * AST + c * 8) * 2, Kp + (size_t)r * HDIM + c * 8);
            cpa16(sb + (AS_V + r * AST + c * 8) * 2, Vp + (size_t)r * HDIM + c * 8);
        }
        CP_COMMIT();
    }
    if (tid < 64) { ms[tid] = -INFINITY; ls[tid] = 0.f; }

    float o[8][4];
#pragma unroll
    for (int nt = 0; nt < 8; nt++)
#pragma unroll
        for (int i = 0; i < 4; i++) o[nt][i] = 0.f;

    for (int t = 0; t < 64; t++) {
        if (t + 1 < 64) {
            const int k1 = (t + 1) * 64, buf = (t + 1) & 1;
#pragma unroll
            for (int i = 0; i < 4; i++) {
                int lin = tid + 256 * i;
                int r = lin >> 4, c = lin & 15;
                cpa16(sb + (AS_K + buf * 64 * AST + r * AST + c * 8) * 2,
                      Kp + (size_t)(k1 + r) * HDIM + c * 8);
                cpa16(sb + (AS_V + buf * 64 * AST + r * AST + c * 8) * 2,
                      Vp + (size_t)(k1 + r) * HDIM + c * 8);
            }
            CP_COMMIT();
            CP_WAIT(1);
        } else {
            CP_WAIT(0);
        }
        __syncthreads();
        const uint32_t kbase = AS_K + (uint32_t)(t & 1) * 64 * AST;
        const uint32_t vbase = AS_V + (uint32_t)(t & 1) * 64 * AST;

        // ---- scores: S = Q @ K^T (warp 16q x 32k) ----
        float s[4][4];
#pragma unroll
        for (int nt = 0; nt < 4; nt++)
#pragma unroll
            for (int i = 0; i < 4; i++) s[nt][i] = 0.f;

#pragma unroll
        for (int kk = 0; kk < 8; kk++) {
            uint32_t a[4], b[4][2];
            {
                int row = wm16 + (lane & 15);
                int col = kk * 16 + (lane >> 4) * 8;
                ldsm4(a[0], a[1], a[2], a[3], sb + (AS_Q + row * AST + col) * 2);
            }
#pragma unroll
            for (int ntp = 0; ntp < 2; ntp++) {
                int row = wn32 + ntp * 16 + (lane & 7) + ((lane >> 4) & 1) * 8;
                int col = kk * 16 + ((lane >> 3) & 1) * 8;
                ldsm4(b[2 * ntp][0], b[2 * ntp][1], b[2 * ntp + 1][0], b[2 * ntp + 1][1],
                      sb + (kbase + row * AST + col) * 2);
            }
#pragma unroll
            for (int nt = 0; nt < 4; nt++)
                mma_f16(s[nt], a, b[nt]);
        }
        // P writeback via stmatrix (2 x4 per warp)
#pragma unroll
        for (int ntp = 0; ntp < 2; ntp++) {
            int tl = lane >> 3;
            int g2 = tl & 1, ntl = ntp * 2 + (tl >> 1);
            int row = wm16 + 8 * g2 + (lane & 7);
            int col = wn32 + 8 * ntl;
            stsm4(sb + (AS_P + row * APS + col) * 2,
                  pack_h2(s[2 * ntp][0], s[2 * ntp][1]),
                  pack_h2(s[2 * ntp][2], s[2 * ntp][3]),
                  pack_h2(s[2 * ntp + 1][0], s[2 * ntp + 1][1]),
                  pack_h2(s[2 * ntp + 1][2], s[2 * ntp + 1][3]));
        }
        __syncthreads();

        // ---- online softmax (4 threads/row, fp32 stats) ----
        {
            __half2* prow = (__half2*)(smh + AS_P + srow * APS + sseg);
            float pv[16];
            float mloc = -INFINITY;
#pragma unroll
            for (int j = 0; j < 8; j++) {
                float2 f = __half22float2(prow[j]);
                pv[2 * j] = f.x; pv[2 * j + 1] = f.y;
                mloc = fmaxf(mloc, fmaxf(f.x, f.y));
            }
            mloc = fmaxf(mloc, __shfl_xor_sync(0xffffffffu, mloc, 1));
            mloc = fmaxf(mloc, __shfl_xor_sync(0xffffffffu, mloc, 2));
            float mold = ms[srow];
            float mnew = fmaxf(mold, mloc);
            float sum = 0.f;
#pragma unroll
            for (int j = 0; j < 8; j++) {
                float e0 = __expf(pv[2 * j] - mnew);
                float e1 = __expf(pv[2 * j + 1] - mnew);
                prow[j] = __floats2half2_rn(e0, e1);
                sum += e0 + e1;
            }
            sum += __shfl_xor_sync(0xffffffffu, sum, 1);
            sum += __shfl_xor_sync(0xffffffffu, sum, 2);
            if ((tid & 3) == 0) {
                float a = __expf(mold - mnew);
                als[srow] = a;
                ms[srow] = mnew;
                ls[srow] = ls[srow] * a + sum;
            }
        }
        __syncthreads();

        // ---- rescale, then O += P @ V ----
        {
            float a_lo = als[wm16 + gr];
            float a_hi = als[wm16 + gr + 8];
#pragma unroll
            for (int nt = 0; nt < 8; nt++) {
                o[nt][0] *= a_lo; o[nt][1] *= a_lo;
                o[nt][2] *= a_hi; o[nt][3] *= a_hi;
            }
        }
#pragma unroll
        for (int kk = 0; kk < 4; kk++) {
            uint32_t a[4];
            {
                int row = wm16 + (lane & 15);
                int col = kk * 16 + (lane >> 4) * 8;
                ldsm4(a[0], a[1], a[2], a[3], sb + (AS_P + row * APS + col) * 2);
            }
            const int vrow = kk * 16 + (lane & 7) + ((lane >> 4) << 3);
#pragma unroll
            for (int nt2 = 0; nt2 < 4; nt2++) {
                int vcol = wn64 + nt2 * 16 + ((lane >> 3) & 1) * 8;
                uint32_t r0, r1, r2, r3;
                ldsm4t(r0, r1, r2, r3, sb + (vbase + vrow * AST + vcol) * 2);
                uint32_t b0[2] = {r0, r2};
                uint32_t b1[2] = {r1, r3};
                mma_f16(o[nt2 * 2],     a, b0);
                mma_f16(o[nt2 * 2 + 1], a, b1);
            }
        }
        __syncthreads();
    }

    // ---- finalize: divide by l, hi/lo split store ----
    {
        int r = wm16 + gr;
        float inv_lo = 1.f / ls[r];
        float inv_hi = 1.f / ls[r + 8];
#pragma unroll
        for (int nt = 0; nt < 8; nt++) {
            int c = wn64 + nt * 8 + 2 * qc;
            size_t o0 = (size_t)(q0 + r) * DMODEL + h * HDIM + c;
            size_t o1 = (size_t)(q0 + r + 8) * DMODEL + h * HDIM + c;
            float v00 = o[nt][0] * inv_lo, v01 = o[nt][1] * inv_lo;
            float v10 = o[nt][2] * inv_hi, v11 = o[nt][3] * inv_hi;
            __half h00 = __float2half(v00), h01 = __float2half(v01);
            __half h10 = __float2half(v10), h11 = __float2half(v11);
            *(uint32_t*)(AOhi + o0) = pack_h2(__half2float(h00), __half2float(h01));
            *(uint32_t*)(AOhi + o1) = pack_h2(__half2float(h10), __half2float(h11));
            *(uint32_t*)(AOlo + o0) = pack_h2(v00 - __half2float(h00), v01 - __half2float(h01));
            *(uint32_t*)(AOlo + o1) = pack_h2(v10 - __half2float(h10), v11 - __half2float(h11));
        }
    }
}

// ---------------------------------------------------------------------------
// launch
// ---------------------------------------------------------------------------
extern "C" void kernel_launch(void* const* d_in, const int* in_sizes, int n_in,
                              void* d_out, int out_size) {
    (void)in_sizes; (void)n_in; (void)out_size;
    const float* X  = (const float*)d_in[0];
    const float* Wq = (const float*)d_in[1];
    const float* Wk = (const float*)d_in[2];
    const float* Wv = (const float*)d_in[3];
    const float* Wo = (const float*)d_in[4];
    float* out = (float*)d_out;

    float* QKVp;
    __half *Wt, *Wot, *Xhi, *Xlo, *Qh, *Kh, *Vh, *AOhi, *AOlo;
    cudaGetSymbolAddress((void**)&QKVp, g_QKV);
    cudaGetSymbolAddress((void**)&Wt, g_Wt);
    cudaGetSymbolAddress((void**)&Wot, g_Wot);
    cudaGetSymbolAddress((void**)&Xhi, g_Xhi);
    cudaGetSymbolAddress((void**)&Xlo, g_Xlo);
    cudaGetSymbolAddress((void**)&Qh, g_Qh);
    cudaGetSymbolAddress((void**)&Kh, g_Kh);
    cudaGetSymbolAddress((void**)&Vh, g_Vh);
    cudaGetSymbolAddress((void**)&AOhi, g_AOhi);
    cudaGetSymbolAddress((void**)&AOlo, g_AOlo);

    cudaFuncSetAttribute(gemm_asplit, cudaFuncAttributeMaxDynamicSharedMemorySize,
                         GEMM_SMEM_BYTES);
    cudaFuncSetAttribute(attn2, cudaFuncAttributeMaxDynamicSharedMemorySize,
                         ATTN_SMEM_BYTES);

    // 1) weight transposes + X split
    transpose_f16<<<dim3(64, 64), dim3(32, 8)>>>(Wq, Wt, DMODEL, 2048);
    transpose_f16<<<dim3(16, 64), dim3(32, 8)>>>(Wk, Wt + 2048 * DMODEL, DMODEL, 512);
    transpose_f16<<<dim3(16, 64), dim3(32, 8)>>>(Wv, Wt + 2560 * DMODEL, DMODEL, 512);
    transpose_f16<<<dim3(64, 64), dim3(32, 8)>>>(Wo, Wot, DMODEL, 2048);
    split_x<<<SEQ * DMODEL / 4 / 256, 256>>>(X, Xhi, Xlo, SEQ * DMODEL / 4);

    // 2) fused QKV projection (A-split fp16 tensor path)
    gemm_asplit<<<dim3(NQKV / 128, SEQ / 128), 256, GEMM_SMEM_BYTES>>>(
        Xhi, Xlo, Wt, QKVp, NQKV, DMODEL);

    // 3) RoPE + per-head fp16 planes
    rope_convert<<<SEQ, 256>>>(QKVp, Qh, Kh, Vh);

    // 4) attention (writes AO hi/lo split)
    attn2<<<dim3(SEQ / 64, NHEAD), 256, ATTN_SMEM_BYTES>>>(Qh, Kh, Vh, AOhi, AOlo);

    // 5) output projection (A-split exact)
    gemm_asplit<<<dim3(DMODEL / 128, SEQ / 128), 256, GEMM_SMEM_BYTES>>>(
        AOhi, AOlo, Wot, out, DMODEL, DMODEL);
}